// round 3
// baseline (speedup 1.0000x reference)
#include <cuda_runtime.h>

typedef unsigned long long u64;

// ---------------- f32x2 helpers (packed: two particles per thread) ----------------
__device__ __forceinline__ u64 pk2(float lo, float hi) {
    u64 r; asm("mov.b64 %0, {%1, %2};" : "=l"(r) : "f"(lo), "f"(hi)); return r;
}
__device__ __forceinline__ void upk2(u64 v, float& lo, float& hi) {
    asm("mov.b64 {%0, %1}, %2;" : "=f"(lo), "=f"(hi) : "l"(v));
}
__device__ __forceinline__ u64 fma2_(u64 a, u64 b, u64 c) {
    u64 d; asm("fma.rn.f32x2 %0, %1, %2, %3;" : "=l"(d) : "l"(a), "l"(b), "l"(c)); return d;
}
__device__ __forceinline__ u64 mul2_(u64 a, u64 b) {
    u64 d; asm("mul.rn.f32x2 %0, %1, %2;" : "=l"(d) : "l"(a), "l"(b)); return d;
}
__device__ __forceinline__ u64 add2_(u64 a, u64 b) {
    u64 d; asm("add.rn.f32x2 %0, %1, %2;" : "=l"(d) : "l"(a), "l"(b)); return d;
}
__device__ __forceinline__ float ex2f_(float x) {
    float y; asm("ex2.approx.f32 %0, %1;" : "=f"(y) : "f"(x)); return y;
}
__device__ __forceinline__ float rcpf_(float x) {
    float y; asm("rcp.approx.f32 %0, %1;" : "=f"(y) : "f"(x)); return y;
}

// scalar-coefficient float2 ops: coefficient is a literal -> FFMA-imm (rt 1)
__device__ __forceinline__ float2 f2fma(float a, float2 b, float2 c) {
    return make_float2(fmaf(a, b.x, c.x), fmaf(a, b.y, c.y));
}
__device__ __forceinline__ float2 f2mul(float a, float2 b) {
    return make_float2(a * b.x, a * b.y);
}

// accurate tanh pair: tanh(x) = 1 - 2/(1 + e^{2x});  2 MUFU per lane, ~1e-7 abs err
__device__ __forceinline__ u64 tanh2_(u64 g, u64 kl2, u64 one2, u64 m2) {
    u64 p = mul2_(g, kl2);            // 2x * log2(e)
    float pl, ph; upk2(p, pl, ph);
    u64 e = pk2(ex2f_(pl), ex2f_(ph));
    u64 s = add2_(e, one2);
    float sl, sh; upk2(s, sl, sh);
    u64 r = pk2(rcpf_(sl), rcpf_(sh));
    return fma2_(m2, r, one2);        // 1 - 2r
}

// ---------------- dynamics for a particle pair ----------------
// sw[j][0..15] duplicated-f32x2 weights:
//   0:W1[j,0] 1:W1[j,1] 2:wb1 3:bb1 4:Wo1  5:W2[j,0] 6:W2[j,1] 7:wb2 8:bb2 9:Wo2
//   10:W3[j,0] 11:W3[j,1] 12:W3[j,2] 13:wb3 14:bb3 15:Wo3
__device__ __forceinline__ void dyn2(float t, float2 X0, float2 X1, float2 X2,
                                     float2& K0, float2& K1, float2& K2,
                                     const u64 (*sw)[16],
                                     u64 kl2, u64 one2, u64 m2) {
    u64 x0 = pk2(X0.x, X0.y);
    u64 x1 = pk2(X1.x, X1.y);
    u64 x2 = pk2(X2.x, X2.y);
    u64 tt = pk2(t, t);
    u64 a1 = 0ULL, a2 = 0ULL, a3 = 0ULL;

    #pragma unroll 4
    for (int j = 0; j < 64; j++) {
        const ulonglong2* p = reinterpret_cast<const ulonglong2*>(sw[j]);
        ulonglong2 q0 = p[0], q1 = p[1], q2 = p[2], q3 = p[3];
        ulonglong2 q4 = p[4], q5 = p[5], q6 = p[6], q7 = p[7];

        // net 1: z @ W1.T + wb1*t + bb1
        u64 g1 = fma2_(q1.x, tt, q1.y);
        g1 = fma2_(q0.x, x0, g1);
        g1 = fma2_(q0.y, x1, g1);
        a1 = fma2_(q2.x, tanh2_(g1, kl2, one2, m2), a1);

        // net 2
        u64 g2 = fma2_(q3.y, tt, q4.x);
        g2 = fma2_(q2.y, x0, g2);
        g2 = fma2_(q3.x, x1, g2);
        a2 = fma2_(q4.y, tanh2_(g2, kl2, one2, m2), a2);

        // net 3 (uses all 3 state components)
        u64 g3 = fma2_(q6.y, tt, q7.x);
        g3 = fma2_(q5.x, x0, g3);
        g3 = fma2_(q5.y, x1, g3);
        g3 = fma2_(q6.x, x2, g3);
        a3 = fma2_(q7.y, tanh2_(g3, kl2, one2, m2), a3);
    }
    float lo, hi;
    upk2(a1, lo, hi); K0 = make_float2(lo, hi);
    upk2(a2, lo, hi); K1 = make_float2(lo, hi);
    upk2(a3, lo, hi); K2 = make_float2(lo, hi);
}

// ---------------- one fully-unrolled DOPRI5 step, all k's in registers ----------------
__device__ __forceinline__ void dopri5_step(float t, float h,
                                            float2& x0, float2& x1, float2& x2,
                                            const u64 (*sw)[16],
                                            u64 kl2, u64 one2, u64 m2) {
    float2 k10,k11,k12, k20,k21,k22, k30,k31,k32,
           k40,k41,k42, k50,k51,k52, k60,k61,k62;
    float2 a0, a1, a2, s0, s1, s2;

    // stage 1
    dyn2(t, x0, x1, x2, k10, k11, k12, sw, kl2, one2, m2);

    // stage 2: x + h*(k1/5)
    a0 = f2mul(0.2f, k10); a1 = f2mul(0.2f, k11); a2 = f2mul(0.2f, k12);
    s0 = f2fma(h, a0, x0); s1 = f2fma(h, a1, x1); s2 = f2fma(h, a2, x2);
    dyn2(fmaf(0.2f, h, t), s0, s1, s2, k20, k21, k22, sw, kl2, one2, m2);

    // stage 3: x + h*(3/40 k1 + 9/40 k2)
    a0 = f2mul(0.075f, k10); a1 = f2mul(0.075f, k11); a2 = f2mul(0.075f, k12);
    a0 = f2fma(0.225f, k20, a0); a1 = f2fma(0.225f, k21, a1); a2 = f2fma(0.225f, k22, a2);
    s0 = f2fma(h, a0, x0); s1 = f2fma(h, a1, x1); s2 = f2fma(h, a2, x2);
    dyn2(fmaf(0.3f, h, t), s0, s1, s2, k30, k31, k32, sw, kl2, one2, m2);

    // stage 4: x + h*(44/45 k1 - 56/15 k2 + 32/9 k3)
    {
        const float c1 = (float)(44.0/45.0), c2 = (float)(-56.0/15.0), c3 = (float)(32.0/9.0);
        a0 = f2mul(c1, k10); a1 = f2mul(c1, k11); a2 = f2mul(c1, k12);
        a0 = f2fma(c2, k20, a0); a1 = f2fma(c2, k21, a1); a2 = f2fma(c2, k22, a2);
        a0 = f2fma(c3, k30, a0); a1 = f2fma(c3, k31, a1); a2 = f2fma(c3, k32, a2);
    }
    s0 = f2fma(h, a0, x0); s1 = f2fma(h, a1, x1); s2 = f2fma(h, a2, x2);
    dyn2(fmaf(0.8f, h, t), s0, s1, s2, k40, k41, k42, sw, kl2, one2, m2);

    // stage 5
    {
        const float c1 = (float)(19372.0/6561.0), c2 = (float)(-25360.0/2187.0),
                    c3 = (float)(64448.0/6561.0), c4 = (float)(-212.0/729.0);
        a0 = f2mul(c1, k10); a1 = f2mul(c1, k11); a2 = f2mul(c1, k12);
        a0 = f2fma(c2, k20, a0); a1 = f2fma(c2, k21, a1); a2 = f2fma(c2, k22, a2);
        a0 = f2fma(c3, k30, a0); a1 = f2fma(c3, k31, a1); a2 = f2fma(c3, k32, a2);
        a0 = f2fma(c4, k40, a0); a1 = f2fma(c4, k41, a1); a2 = f2fma(c4, k42, a2);
    }
    s0 = f2fma(h, a0, x0); s1 = f2fma(h, a1, x1); s2 = f2fma(h, a2, x2);
    dyn2(fmaf((float)(8.0/9.0), h, t), s0, s1, s2, k50, k51, k52, sw, kl2, one2, m2);

    // stage 6
    {
        const float c1 = (float)(9017.0/3168.0), c2 = (float)(-355.0/33.0),
                    c3 = (float)(46732.0/5247.0), c4 = (float)(49.0/176.0),
                    c5 = (float)(-5103.0/18656.0);
        a0 = f2mul(c1, k10); a1 = f2mul(c1, k11); a2 = f2mul(c1, k12);
        a0 = f2fma(c2, k20, a0); a1 = f2fma(c2, k21, a1); a2 = f2fma(c2, k22, a2);
        a0 = f2fma(c3, k30, a0); a1 = f2fma(c3, k31, a1); a2 = f2fma(c3, k32, a2);
        a0 = f2fma(c4, k40, a0); a1 = f2fma(c4, k41, a1); a2 = f2fma(c4, k42, a2);
        a0 = f2fma(c5, k50, a0); a1 = f2fma(c5, k51, a1); a2 = f2fma(c5, k52, a2);
    }
    s0 = f2fma(h, a0, x0); s1 = f2fma(h, a1, x1); s2 = f2fma(h, a2, x2);
    dyn2(t + h, s0, s1, s2, k60, k61, k62, sw, kl2, one2, m2);

    // combine: x += h * (b1 k1 + b3 k3 + b4 k4 + b5 k5 + b6 k6)
    {
        const float b1 = (float)(35.0/384.0), b3 = (float)(500.0/1113.0),
                    b4 = (float)(125.0/192.0), b5 = (float)(-2187.0/6784.0),
                    b6 = (float)(11.0/84.0);
        a0 = f2mul(b1, k10); a1 = f2mul(b1, k11); a2 = f2mul(b1, k12);
        a0 = f2fma(b3, k30, a0); a1 = f2fma(b3, k31, a1); a2 = f2fma(b3, k32, a2);
        a0 = f2fma(b4, k40, a0); a1 = f2fma(b4, k41, a1); a2 = f2fma(b4, k42, a2);
        a0 = f2fma(b5, k50, a0); a1 = f2fma(b5, k51, a1); a2 = f2fma(b5, k52, a2);
        a0 = f2fma(b6, k60, a0); a1 = f2fma(b6, k61, a1); a2 = f2fma(b6, k62, a2);
    }
    x0 = f2fma(h, a0, x0); x1 = f2fma(h, a1, x1); x2 = f2fma(h, a2, x2);
}

// ---------------- main kernel ----------------
extern "C" __global__ void __launch_bounds__(128, 4)
ode_kernel(const float* __restrict__ u,
           const float* __restrict__ W1, const float* __restrict__ W2, const float* __restrict__ W3,
           const float* __restrict__ wb1, const float* __restrict__ bb1,
           const float* __restrict__ wb2, const float* __restrict__ bb2,
           const float* __restrict__ wb3, const float* __restrict__ bb3,
           const float* __restrict__ Wo1, const float* __restrict__ Wo2, const float* __restrict__ Wo3,
           float* __restrict__ out, int B)
{
    __shared__ __align__(16) u64 sw[64][16];
    int tid = threadIdx.x;
    for (int idx = tid; idx < 64 * 16; idx += blockDim.x) {
        int j = idx >> 4, f = idx & 15;
        float v;
        switch (f) {
            case 0:  v = W1[2*j];    break;
            case 1:  v = W1[2*j+1];  break;
            case 2:  v = wb1[j];     break;
            case 3:  v = bb1[j];     break;
            case 4:  v = Wo1[j];     break;
            case 5:  v = W2[2*j];    break;
            case 6:  v = W2[2*j+1];  break;
            case 7:  v = wb2[j];     break;
            case 8:  v = bb2[j];     break;
            case 9:  v = Wo2[j];     break;
            case 10: v = W3[3*j];    break;
            case 11: v = W3[3*j+1];  break;
            case 12: v = W3[3*j+2];  break;
            case 13: v = wb3[j];     break;
            case 14: v = bb3[j];     break;
            default: v = Wo3[j];     break;
        }
        sw[j][f] = pk2(v, v);
    }
    __syncthreads();

    const u64 kl2  = pk2(2.885390081777927f, 2.885390081777927f);  // 2*log2(e)
    const u64 one2 = pk2(1.0f, 1.0f);
    const u64 m2   = pk2(-2.0f, -2.0f);

    const int npairs = B >> 1;
    int pid = blockIdx.x * blockDim.x + tid;   // one particle pair per thread
    if (pid >= npairs) return;

    const float* up = u + 6 * pid;
    float u0 = up[0], u1 = up[1], u2 = up[2];
    float u3 = up[3], u4 = up[4], u5 = up[5];

    // ---- phase 0: features, 24 steps, h = 10/24, t0 = 0 ----
    {
        float2 x0 = make_float2(u0, u3);
        float2 x1 = make_float2(u1, u4);
        float2 x2 = make_float2(u2, u5);
        const float h = (float)(10.0/24.0);
        float t = 0.0f;
        #pragma unroll 1
        for (int it = 0; it < 24; it++) {
            dopri5_step(t, h, x0, x1, x2, sw, kl2, one2, m2);
            t += h;
        }
        float* of = out + 6 * pid;
        of[0] = x0.x; of[1] = x1.x; of[2] = x2.x;
        of[3] = x0.y; of[4] = x1.y; of[5] = x2.y;
    }

    // ---- phase 1: trajectory, 9 segments x 3 substeps, h = 10/27 ----
    {
        float2 x0 = make_float2(u0, u3);
        float2 x1 = make_float2(u1, u4);
        float2 x2 = make_float2(u2, u5);
        const float h = (float)(10.0/27.0);
        #pragma unroll 1
        for (int sg = 0; sg < 9; sg++) {
            float t = (float)sg * (float)(10.0/9.0);
            #pragma unroll 1
            for (int it = 0; it < 3; it++) {
                dopri5_step(t, h, x0, x1, x2, sw, kl2, one2, m2);
                t += h;
            }
            float* ot = out + (size_t)3 * B + (size_t)sg * 3 * B + 6 * pid;
            ot[0] = x0.x; ot[1] = x1.x; ot[2] = x2.x;
            ot[3] = x0.y; ot[4] = x1.y; ot[5] = x2.y;
        }
    }
}

extern "C" void kernel_launch(void* const* d_in, const int* in_sizes, int n_in,
                              void* d_out, int out_size) {
    const float* u   = (const float*)d_in[0];
    const float* W1  = (const float*)d_in[1];
    const float* W2  = (const float*)d_in[2];
    const float* W3  = (const float*)d_in[3];
    const float* wb1 = (const float*)d_in[4];
    const float* bb1 = (const float*)d_in[5];
    const float* wb2 = (const float*)d_in[6];
    const float* bb2 = (const float*)d_in[7];
    const float* wb3 = (const float*)d_in[8];
    const float* bb3 = (const float*)d_in[9];
    const float* Wo1 = (const float*)d_in[10];
    const float* Wo2 = (const float*)d_in[11];
    const float* Wo3 = (const float*)d_in[12];
    float* out = (float*)d_out;
    int B = in_sizes[0] / 3;

    int npairs = B >> 1;
    int blocks = (npairs + 127) / 128;
    ode_kernel<<<blocks, 128>>>(u, W1, W2, W3, wb1, bb1, wb2, bb2, wb3, bb3,
                                Wo1, Wo2, Wo3, out, B);
}

// round 4
// speedup vs baseline: 3.0232x; 3.0232x over previous
#include <cuda_runtime.h>

typedef unsigned long long u64;

// ---------------- DOPRI5 coefficients ----------------
__constant__ float cA[15] = {
    (float)(1.0/5.0),
    (float)(3.0/40.0), (float)(9.0/40.0),
    (float)(44.0/45.0), (float)(-56.0/15.0), (float)(32.0/9.0),
    (float)(19372.0/6561.0), (float)(-25360.0/2187.0), (float)(64448.0/6561.0), (float)(-212.0/729.0),
    (float)(9017.0/3168.0), (float)(-355.0/33.0), (float)(46732.0/5247.0), (float)(49.0/176.0), (float)(-5103.0/18656.0)
};
__constant__ float cB[6] = {
    (float)(35.0/384.0), 0.0f, (float)(500.0/1113.0),
    (float)(125.0/192.0), (float)(-2187.0/6784.0), (float)(11.0/84.0)
};
__constant__ float cC[6] = { 0.0f, (float)(1.0/5.0), (float)(3.0/10.0),
                             (float)(4.0/5.0), (float)(8.0/9.0), 1.0f };

// ---------------- f32x2 helpers (packed: two particles per thread) ----------------
__device__ __forceinline__ u64 pk2(float lo, float hi) {
    u64 r; asm("mov.b64 %0, {%1, %2};" : "=l"(r) : "f"(lo), "f"(hi)); return r;
}
__device__ __forceinline__ void upk2(u64 v, float& lo, float& hi) {
    asm("mov.b64 {%0, %1}, %2;" : "=f"(lo), "=f"(hi) : "l"(v));
}
__device__ __forceinline__ u64 fma2_(u64 a, u64 b, u64 c) {
    u64 d; asm("fma.rn.f32x2 %0, %1, %2, %3;" : "=l"(d) : "l"(a), "l"(b), "l"(c)); return d;
}

__device__ __forceinline__ float tanhap_(float x) {
    float y; asm("tanh.approx.f32 %0, %1;" : "=f"(y) : "f"(x)); return y;
}

// single-MUFU-per-lane tanh pair (HW tanh.approx)
__device__ __forceinline__ u64 tanh2a_(u64 g) {
    float l, h; upk2(g, l, h);
    return pk2(tanhap_(l), tanhap_(h));
}

__device__ __forceinline__ float2 f2fma(float a, float2 b, float2 c) {
    return make_float2(fmaf(a, b.x, c.x), fmaf(a, b.y, c.y));
}

// ---------------- dynamics: dx = [h1@Wo1, h2@Wo2, h3@Wo3] for a particle pair ----------------
// sw[j][0..15] = duplicated-f32x2 weights:
//   0:W1[j,0] 1:W1[j,1] 2:wb1 3:bb1 4:Wo1  5:W2[j,0] 6:W2[j,1] 7:wb2 8:bb2 9:Wo2
//   10:W3[j,0] 11:W3[j,1] 12:W3[j,2] 13:wb3 14:bb3 15:Wo3
__device__ __forceinline__ void dyn2(float t, float2 X0, float2 X1, float2 X2,
                                     float2* kk, const u64 (*sw)[16]) {
    u64 x0 = pk2(X0.x, X0.y);
    u64 x1 = pk2(X1.x, X1.y);
    u64 x2 = pk2(X2.x, X2.y);
    u64 tt = pk2(t, t);
    u64 a1 = 0ULL, a2 = 0ULL, a3 = 0ULL;

    #pragma unroll 4
    for (int j = 0; j < 64; j++) {
        const ulonglong2* p = reinterpret_cast<const ulonglong2*>(sw[j]);
        ulonglong2 q0 = p[0], q1 = p[1], q2 = p[2], q3 = p[3];
        ulonglong2 q4 = p[4], q5 = p[5], q6 = p[6], q7 = p[7];

        // net 1: z @ W1.T + wb1*t + bb1
        u64 g1 = fma2_(q1.x, tt, q1.y);
        g1 = fma2_(q0.x, x0, g1);
        g1 = fma2_(q0.y, x1, g1);
        a1 = fma2_(q2.x, tanh2a_(g1), a1);

        // net 2
        u64 g2 = fma2_(q3.y, tt, q4.x);
        g2 = fma2_(q2.y, x0, g2);
        g2 = fma2_(q3.x, x1, g2);
        a2 = fma2_(q4.y, tanh2a_(g2), a2);

        // net 3 (uses all 3 state components)
        u64 g3 = fma2_(q6.y, tt, q7.x);
        g3 = fma2_(q5.x, x0, g3);
        g3 = fma2_(q5.y, x1, g3);
        g3 = fma2_(q6.x, x2, g3);
        a3 = fma2_(q7.y, tanh2a_(g3), a3);
    }
    float lo, hi;
    upk2(a1, lo, hi); kk[0] = make_float2(lo, hi);
    upk2(a2, lo, hi); kk[1] = make_float2(lo, hi);
    upk2(a3, lo, hi); kk[2] = make_float2(lo, hi);
}

// ---------------- main kernel ----------------
extern "C" __global__ void __launch_bounds__(128, 4)
ode_kernel(const float* __restrict__ u,
           const float* __restrict__ W1, const float* __restrict__ W2, const float* __restrict__ W3,
           const float* __restrict__ wb1, const float* __restrict__ bb1,
           const float* __restrict__ wb2, const float* __restrict__ bb2,
           const float* __restrict__ wb3, const float* __restrict__ bb3,
           const float* __restrict__ Wo1, const float* __restrict__ Wo2, const float* __restrict__ Wo3,
           float* __restrict__ out, int B)
{
    __shared__ __align__(16) u64 sw[64][16];
    int tid = threadIdx.x;
    for (int idx = tid; idx < 64 * 16; idx += blockDim.x) {
        int j = idx >> 4, f = idx & 15;
        float v;
        switch (f) {
            case 0:  v = W1[2*j];    break;
            case 1:  v = W1[2*j+1];  break;
            case 2:  v = wb1[j];     break;
            case 3:  v = bb1[j];     break;
            case 4:  v = Wo1[j];     break;
            case 5:  v = W2[2*j];    break;
            case 6:  v = W2[2*j+1];  break;
            case 7:  v = wb2[j];     break;
            case 8:  v = bb2[j];     break;
            case 9:  v = Wo2[j];     break;
            case 10: v = W3[3*j];    break;
            case 11: v = W3[3*j+1];  break;
            case 12: v = W3[3*j+2];  break;
            case 13: v = wb3[j];     break;
            case 14: v = bb3[j];     break;
            default: v = Wo3[j];     break;
        }
        sw[j][f] = pk2(v, v);
    }
    __syncthreads();

    const int npairs = B >> 1;
    int pid = blockIdx.x * blockDim.x + tid;   // one particle pair per thread
    if (pid >= npairs) return;

    {
        const float* up = u + 6 * pid;
        float u0 = up[0], u1 = up[1], u2 = up[2];
        float u3 = up[3], u4 = up[4], u5 = up[5];

        #pragma unroll 1
        for (int phase = 0; phase < 2; phase++) {
            float2 x0 = make_float2(u0, u3);
            float2 x1 = make_float2(u1, u4);
            float2 x2 = make_float2(u2, u5);
            const float h   = phase ? (float)(10.0/27.0) : (float)(10.0/24.0);
            const int nseg  = phase ? 9 : 1;
            const int nsub  = phase ? 3 : 24;

            #pragma unroll 1
            for (int sg = 0; sg < nseg; sg++) {
                float t = phase ? (float)sg * (float)(10.0/9.0) : 0.0f;

                #pragma unroll 1
                for (int it = 0; it < nsub; it++) {
                    float2 k[6][3];   // dynamic-indexed -> local mem (cheap vs compute)
                    #pragma unroll 1
                    for (int s = 0; s < 6; s++) {
                        float2 a0 = make_float2(0.f, 0.f);
                        float2 a1 = make_float2(0.f, 0.f);
                        float2 a2 = make_float2(0.f, 0.f);
                        int base = (s * (s - 1)) >> 1;
                        for (int m = 0; m < s; m++) {
                            float a = cA[base + m];
                            a0 = f2fma(a, k[m][0], a0);
                            a1 = f2fma(a, k[m][1], a1);
                            a2 = f2fma(a, k[m][2], a2);
                        }
                        float2 xs0 = f2fma(h, a0, x0);
                        float2 xs1 = f2fma(h, a1, x1);
                        float2 xs2 = f2fma(h, a2, x2);
                        float ts = fmaf(cC[s], h, t);
                        dyn2(ts, xs0, xs1, xs2, k[s], sw);
                    }
                    // x += h * (b1 k1 + b3 k3 + b4 k4 + b5 k5 + b6 k6)
                    float2 a0 = make_float2(0.f, 0.f);
                    float2 a1 = make_float2(0.f, 0.f);
                    float2 a2 = make_float2(0.f, 0.f);
                    for (int m = 0; m < 6; m++) {
                        float b = cB[m];
                        a0 = f2fma(b, k[m][0], a0);
                        a1 = f2fma(b, k[m][1], a1);
                        a2 = f2fma(b, k[m][2], a2);
                    }
                    x0 = f2fma(h, a0, x0);
                    x1 = f2fma(h, a1, x1);
                    x2 = f2fma(h, a2, x2);
                    t += h;
                }

                if (phase) {
                    float* ot = out + (size_t)3 * B + (size_t)sg * 3 * B + 6 * pid;
                    ot[0] = x0.x; ot[1] = x1.x; ot[2] = x2.x;
                    ot[3] = x0.y; ot[4] = x1.y; ot[5] = x2.y;
                }
            }
            if (!phase) {
                float* of = out + 6 * pid;
                of[0] = x0.x; of[1] = x1.x; of[2] = x2.x;
                of[3] = x0.y; of[4] = x1.y; of[5] = x2.y;
            }
        }
    }
}

extern "C" void kernel_launch(void* const* d_in, const int* in_sizes, int n_in,
                              void* d_out, int out_size) {
    const float* u   = (const float*)d_in[0];
    const float* W1  = (const float*)d_in[1];
    const float* W2  = (const float*)d_in[2];
    const float* W3  = (const float*)d_in[3];
    const float* wb1 = (const float*)d_in[4];
    const float* bb1 = (const float*)d_in[5];
    const float* wb2 = (const float*)d_in[6];
    const float* bb2 = (const float*)d_in[7];
    const float* wb3 = (const float*)d_in[8];
    const float* bb3 = (const float*)d_in[9];
    const float* Wo1 = (const float*)d_in[10];
    const float* Wo2 = (const float*)d_in[11];
    const float* Wo3 = (const float*)d_in[12];
    float* out = (float*)d_out;
    int B = in_sizes[0] / 3;

    int npairs = B >> 1;
    int blocks = (npairs + 127) / 128;
    ode_kernel<<<blocks, 128>>>(u, W1, W2, W3, wb1, bb1, wb2, bb2, wb3, bb3,
                                Wo1, Wo2, Wo3, out, B);
}

// round 5
// speedup vs baseline: 3.4350x; 1.1362x over previous
#include <cuda_runtime.h>

typedef unsigned long long u64;

// ---------------- DOPRI5 coefficients ----------------
__constant__ float cA[15] = {
    (float)(1.0/5.0),
    (float)(3.0/40.0), (float)(9.0/40.0),
    (float)(44.0/45.0), (float)(-56.0/15.0), (float)(32.0/9.0),
    (float)(19372.0/6561.0), (float)(-25360.0/2187.0), (float)(64448.0/6561.0), (float)(-212.0/729.0),
    (float)(9017.0/3168.0), (float)(-355.0/33.0), (float)(46732.0/5247.0), (float)(49.0/176.0), (float)(-5103.0/18656.0)
};
__constant__ float cB[6] = {
    (float)(35.0/384.0), 0.0f, (float)(500.0/1113.0),
    (float)(125.0/192.0), (float)(-2187.0/6784.0), (float)(11.0/84.0)
};
__constant__ float cC[6] = { 0.0f, (float)(1.0/5.0), (float)(3.0/10.0),
                             (float)(4.0/5.0), (float)(8.0/9.0), 1.0f };

// ---------------- f32x2 helpers ----------------
__device__ __forceinline__ u64 pk2(float lo, float hi) {
    u64 r; asm("mov.b64 %0, {%1, %2};" : "=l"(r) : "f"(lo), "f"(hi)); return r;
}
__device__ __forceinline__ void upk2(u64 v, float& lo, float& hi) {
    asm("mov.b64 {%0, %1}, %2;" : "=f"(lo), "=f"(hi) : "l"(v));
}
__device__ __forceinline__ u64 fma2_(u64 a, u64 b, u64 c) {
    u64 d; asm("fma.rn.f32x2 %0, %1, %2, %3;" : "=l"(d) : "l"(a), "l"(b), "l"(c)); return d;
}
__device__ __forceinline__ float tanhap_(float x) {
    float y; asm("tanh.approx.f32 %0, %1;" : "=f"(y) : "f"(x)); return y;
}
__device__ __forceinline__ u64 tanh2a_(u64 g) {
    float l, h; upk2(g, l, h);
    return pk2(tanhap_(l), tanhap_(h));
}
__device__ __forceinline__ float2 f2fma(float a, float2 b, float2 c) {
    return make_float2(fmaf(a, b.x, c.x), fmaf(a, b.y, c.y));
}

// ---------------- dynamics for FOUR particles (two f32x2 pairs A and B) ----------------
// sw[j][0..15] = duplicated-f32x2 weights:
//   0:W1[j,0] 1:W1[j,1] 2:wb1 3:bb1 4:Wo1  5:W2[j,0] 6:W2[j,1] 7:wb2 8:bb2 9:Wo2
//   10:W3[j,0] 11:W3[j,1] 12:W3[j,2] 13:wb3 14:bb3 15:Wo3
__device__ __forceinline__ void dyn4(float t,
                                     float2 A0, float2 A1, float2 A2,
                                     float2 B0, float2 B1, float2 B2,
                                     float2* kA, float2* kB,
                                     const u64 (*sw)[16]) {
    u64 xa0 = pk2(A0.x, A0.y), xa1 = pk2(A1.x, A1.y), xa2 = pk2(A2.x, A2.y);
    u64 xb0 = pk2(B0.x, B0.y), xb1 = pk2(B1.x, B1.y), xb2 = pk2(B2.x, B2.y);
    u64 tt = pk2(t, t);
    u64 aA1 = 0ULL, aA2 = 0ULL, aA3 = 0ULL;
    u64 aB1 = 0ULL, aB2 = 0ULL, aB3 = 0ULL;

    #pragma unroll 2
    for (int j = 0; j < 64; j++) {
        const ulonglong2* p = reinterpret_cast<const ulonglong2*>(sw[j]);
        ulonglong2 q0 = p[0], q1 = p[1], q2 = p[2], q3 = p[3];
        ulonglong2 q4 = p[4], q5 = p[5], q6 = p[6], q7 = p[7];

        // ---- net 1: bias shared across A/B ----
        u64 b1 = fma2_(q1.x, tt, q1.y);                 // wb1*t + bb1
        u64 gA1 = fma2_(q0.x, xa0, b1); gA1 = fma2_(q0.y, xa1, gA1);
        u64 gB1 = fma2_(q0.x, xb0, b1); gB1 = fma2_(q0.y, xb1, gB1);
        aA1 = fma2_(q2.x, tanh2a_(gA1), aA1);
        aB1 = fma2_(q2.x, tanh2a_(gB1), aB1);

        // ---- net 2 ----
        u64 b2 = fma2_(q3.y, tt, q4.x);                 // wb2*t + bb2
        u64 gA2 = fma2_(q2.y, xa0, b2); gA2 = fma2_(q3.x, xa1, gA2);
        u64 gB2 = fma2_(q2.y, xb0, b2); gB2 = fma2_(q3.x, xb1, gB2);
        aA2 = fma2_(q4.y, tanh2a_(gA2), aA2);
        aB2 = fma2_(q4.y, tanh2a_(gB2), aB2);

        // ---- net 3 (3 state inputs) ----
        u64 b3 = fma2_(q6.y, tt, q7.x);                 // wb3*t + bb3
        u64 gA3 = fma2_(q5.x, xa0, b3); gA3 = fma2_(q5.y, xa1, gA3); gA3 = fma2_(q6.x, xa2, gA3);
        u64 gB3 = fma2_(q5.x, xb0, b3); gB3 = fma2_(q5.y, xb1, gB3); gB3 = fma2_(q6.x, xb2, gB3);
        aA3 = fma2_(q7.y, tanh2a_(gA3), aA3);
        aB3 = fma2_(q7.y, tanh2a_(gB3), aB3);
    }
    float lo, hi;
    upk2(aA1, lo, hi); kA[0] = make_float2(lo, hi);
    upk2(aA2, lo, hi); kA[1] = make_float2(lo, hi);
    upk2(aA3, lo, hi); kA[2] = make_float2(lo, hi);
    upk2(aB1, lo, hi); kB[0] = make_float2(lo, hi);
    upk2(aB2, lo, hi); kB[1] = make_float2(lo, hi);
    upk2(aB3, lo, hi); kB[2] = make_float2(lo, hi);
}

// ---------------- main kernel: 4 particles per thread ----------------
extern "C" __global__ void __launch_bounds__(64, 5)
ode_kernel(const float* __restrict__ u,
           const float* __restrict__ W1, const float* __restrict__ W2, const float* __restrict__ W3,
           const float* __restrict__ wb1, const float* __restrict__ bb1,
           const float* __restrict__ wb2, const float* __restrict__ bb2,
           const float* __restrict__ wb3, const float* __restrict__ bb3,
           const float* __restrict__ Wo1, const float* __restrict__ Wo2, const float* __restrict__ Wo3,
           float* __restrict__ out, int B)
{
    __shared__ __align__(16) u64 sw[64][16];
    int tid = threadIdx.x;
    for (int idx = tid; idx < 64 * 16; idx += blockDim.x) {
        int j = idx >> 4, f = idx & 15;
        float v;
        switch (f) {
            case 0:  v = W1[2*j];    break;
            case 1:  v = W1[2*j+1];  break;
            case 2:  v = wb1[j];     break;
            case 3:  v = bb1[j];     break;
            case 4:  v = Wo1[j];     break;
            case 5:  v = W2[2*j];    break;
            case 6:  v = W2[2*j+1];  break;
            case 7:  v = wb2[j];     break;
            case 8:  v = bb2[j];     break;
            case 9:  v = Wo2[j];     break;
            case 10: v = W3[3*j];    break;
            case 11: v = W3[3*j+1];  break;
            case 12: v = W3[3*j+2];  break;
            case 13: v = wb3[j];     break;
            case 14: v = bb3[j];     break;
            default: v = Wo3[j];     break;
        }
        sw[j][f] = pk2(v, v);
    }
    __syncthreads();

    const int nquads = B >> 2;
    int qid = blockIdx.x * blockDim.x + tid;   // four particles per thread
    if (qid >= nquads) return;

    const float* up = u + 12 * qid;
    float uv[12];
    #pragma unroll
    for (int i = 0; i < 12; i++) uv[i] = up[i];

    #pragma unroll 1
    for (int phase = 0; phase < 2; phase++) {
        // pair A = particles (4q, 4q+1), pair B = (4q+2, 4q+3)
        float2 xA0 = make_float2(uv[0], uv[3]);
        float2 xA1 = make_float2(uv[1], uv[4]);
        float2 xA2 = make_float2(uv[2], uv[5]);
        float2 xB0 = make_float2(uv[6], uv[9]);
        float2 xB1 = make_float2(uv[7], uv[10]);
        float2 xB2 = make_float2(uv[8], uv[11]);
        const float h   = phase ? (float)(10.0/27.0) : (float)(10.0/24.0);
        const int nseg  = phase ? 9 : 1;
        const int nsub  = phase ? 3 : 24;

        #pragma unroll 1
        for (int sg = 0; sg < nseg; sg++) {
            float t = phase ? (float)sg * (float)(10.0/9.0) : 0.0f;

            #pragma unroll 1
            for (int it = 0; it < nsub; it++) {
                float2 kA[6][3], kB[6][3];   // dynamic-indexed -> local (cheap vs compute)
                #pragma unroll 1
                for (int s = 0; s < 6; s++) {
                    float2 aA0 = make_float2(0.f,0.f), aA1 = make_float2(0.f,0.f), aA2 = make_float2(0.f,0.f);
                    float2 aB0 = make_float2(0.f,0.f), aB1 = make_float2(0.f,0.f), aB2 = make_float2(0.f,0.f);
                    int base = (s * (s - 1)) >> 1;
                    for (int m = 0; m < s; m++) {
                        float a = cA[base + m];
                        aA0 = f2fma(a, kA[m][0], aA0);
                        aA1 = f2fma(a, kA[m][1], aA1);
                        aA2 = f2fma(a, kA[m][2], aA2);
                        aB0 = f2fma(a, kB[m][0], aB0);
                        aB1 = f2fma(a, kB[m][1], aB1);
                        aB2 = f2fma(a, kB[m][2], aB2);
                    }
                    float2 sA0 = f2fma(h, aA0, xA0), sA1 = f2fma(h, aA1, xA1), sA2 = f2fma(h, aA2, xA2);
                    float2 sB0 = f2fma(h, aB0, xB0), sB1 = f2fma(h, aB1, xB1), sB2 = f2fma(h, aB2, xB2);
                    float ts = fmaf(cC[s], h, t);
                    dyn4(ts, sA0, sA1, sA2, sB0, sB1, sB2, kA[s], kB[s], sw);
                }
                float2 aA0 = make_float2(0.f,0.f), aA1 = make_float2(0.f,0.f), aA2 = make_float2(0.f,0.f);
                float2 aB0 = make_float2(0.f,0.f), aB1 = make_float2(0.f,0.f), aB2 = make_float2(0.f,0.f);
                for (int m = 0; m < 6; m++) {
                    float b = cB[m];
                    aA0 = f2fma(b, kA[m][0], aA0);
                    aA1 = f2fma(b, kA[m][1], aA1);
                    aA2 = f2fma(b, kA[m][2], aA2);
                    aB0 = f2fma(b, kB[m][0], aB0);
                    aB1 = f2fma(b, kB[m][1], aB1);
                    aB2 = f2fma(b, kB[m][2], aB2);
                }
                xA0 = f2fma(h, aA0, xA0); xA1 = f2fma(h, aA1, xA1); xA2 = f2fma(h, aA2, xA2);
                xB0 = f2fma(h, aB0, xB0); xB1 = f2fma(h, aB1, xB1); xB2 = f2fma(h, aB2, xB2);
                t += h;
            }

            if (phase) {
                float* ot = out + (size_t)3 * B + (size_t)sg * 3 * B + 12 * qid;
                ot[0] = xA0.x; ot[1]  = xA1.x; ot[2]  = xA2.x;
                ot[3] = xA0.y; ot[4]  = xA1.y; ot[5]  = xA2.y;
                ot[6] = xB0.x; ot[7]  = xB1.x; ot[8]  = xB2.x;
                ot[9] = xB0.y; ot[10] = xB1.y; ot[11] = xB2.y;
            }
        }
        if (!phase) {
            float* of = out + 12 * qid;
            of[0] = xA0.x; of[1]  = xA1.x; of[2]  = xA2.x;
            of[3] = xA0.y; of[4]  = xA1.y; of[5]  = xA2.y;
            of[6] = xB0.x; of[7]  = xB1.x; of[8]  = xB2.x;
            of[9] = xB0.y; of[10] = xB1.y; of[11] = xB2.y;
        }
    }
}

extern "C" void kernel_launch(void* const* d_in, const int* in_sizes, int n_in,
                              void* d_out, int out_size) {
    const float* u   = (const float*)d_in[0];
    const float* W1  = (const float*)d_in[1];
    const float* W2  = (const float*)d_in[2];
    const float* W3  = (const float*)d_in[3];
    const float* wb1 = (const float*)d_in[4];
    const float* bb1 = (const float*)d_in[5];
    const float* wb2 = (const float*)d_in[6];
    const float* bb2 = (const float*)d_in[7];
    const float* wb3 = (const float*)d_in[8];
    const float* bb3 = (const float*)d_in[9];
    const float* Wo1 = (const float*)d_in[10];
    const float* Wo2 = (const float*)d_in[11];
    const float* Wo3 = (const float*)d_in[12];
    float* out = (float*)d_out;
    int B = in_sizes[0] / 3;

    int nquads = B >> 2;
    int blocks = (nquads + 63) / 64;
    ode_kernel<<<blocks, 64>>>(u, W1, W2, W3, wb1, bb1, wb2, bb2, wb3, bb3,
                               Wo1, Wo2, Wo3, out, B);
}